// round 3
// baseline (speedup 1.0000x reference)
#include <cuda_runtime.h>
#include <cuda_bf16.h>
#include <stdint.h>

// Problem constants (fixed by the dataset):
//   x:          (80, 2048, 16, 16) f32
//   s_ca:       (80, 2048, 1, 1)   f32
//   rand_index: (80, 512)          int32
//   partner:    (80,)              int32
//   out:        (160, 2048, 16, 16) f32
#define NB   80
#define CCH  2048
#define NQ   64         // HW/4 float4 per channel
#define SSH  512
#define CPB  8          // channels per block

// ---------------------------------------------------------------------------
// Fused kernel: one block = (batch row n, 8 consecutive channels).
//
// Phase 1: load the row's 2048 scores into smem (L2-hot, 8KB).
// Phase 2: warp w computes rank of channel ch0+w via a conflict-free smem
//          scan: rank = #{i : s[i] > s[ch]  or  (s[i]==s[ch] and i < ch)}.
//          rank < 512  <=>  channel is in jax top_k, at list position k=rank
//          (exactly jax's stable ordering, ties broken by lower index).
// Phase 3: DRAM-bound memory work — each thread produces 2 quads of both the
//          plain and augmented output halves from one x read.
// ---------------------------------------------------------------------------
__global__ void __launch_bounds__(256, 6)
fused_shuffle_kernel(const float* __restrict__ x,
                     const float* __restrict__ s_ca,
                     const int*   __restrict__ rand_index,
                     const int*   __restrict__ partner,
                     float*       __restrict__ out)
{
    __shared__ float ss[CCH];
    __shared__ int   srank[CPB];

    const int n   = blockIdx.y;
    const int ch0 = blockIdx.x * CPB;
    const int t   = threadIdx.x;

    // Phase 1: score row -> smem (coalesced, hits L2 after first block per row)
    const float* row = s_ca + (size_t)n * CCH;
#pragma unroll
    for (int i = t; i < CCH; i += 256) ss[i] = __ldg(&row[i]);
    __syncthreads();

    // Phase 2: rank of this warp's channel
    {
        const int w    = t >> 5;
        const int lane = t & 31;
        const int c    = ch0 + w;
        const float kc = ss[c];
        int r = 0;
#pragma unroll 8
        for (int i = lane; i < CCH; i += 32) {
            float v = ss[i];
            r += (v > kc) || (v == kc && i < c);
        }
#pragma unroll
        for (int o = 16; o; o >>= 1) r += __shfl_xor_sync(0xFFFFFFFFu, r, o);
        if (lane == 0) srank[w] = r;
    }
    __syncthreads();

    // Phase 3: memory work. 8 channels x 64 quads = 512 tasks, 2 per thread.
    const int v = n >> 4;          // way
    const int b = n & 15;          // slot within way
    const int jrow = (n + 1 + __ldg(&partner[n])) % NB;

    const float4* x4 = (const float4*)x;
    float4*       o4 = (float4*)out;

#pragma unroll
    for (int it = 0; it < 2; ++it) {
        const int task = it * 256 + t;       // 0..511
        const int ci   = task >> 6;          // channel within block
        const int q    = task & 63;          // float4 quad within channel
        const int ch   = ch0 + ci;
        const float s  = ss[ch];

        float4 xv = x4[((size_t)n * CCH + ch) * NQ + q];

        float4 po;
        po.x = xv.x * s; po.y = xv.y * s; po.z = xv.z * s; po.w = xv.w * s;
        o4[(((size_t)(v * 32 + b)) * CCH + ch) * NQ + q] = po;

        float4 ao = po;
        const int k = srank[ci];             // uniform across each 64-thread group
        if (k < SSH) {
            int rc = __ldg(&rand_index[n * SSH + k]);
            float4 pv = x4[((size_t)jrow * CCH + rc) * NQ + q];
            ao.x = (0.7f * xv.x + 0.3f * pv.x) * s;
            ao.y = (0.7f * xv.y + 0.3f * pv.y) * s;
            ao.z = (0.7f * xv.z + 0.3f * pv.z) * s;
            ao.w = (0.7f * xv.w + 0.3f * pv.w) * s;
        }
        o4[(((size_t)(v * 32 + 16 + b)) * CCH + ch) * NQ + q] = ao;
    }
}

extern "C" void kernel_launch(void* const* d_in, const int* in_sizes, int n_in,
                              void* d_out, int out_size)
{
    const float* x          = (const float*)d_in[0];
    const float* s_ca       = (const float*)d_in[1];
    const int*   rand_index = (const int*)  d_in[2];
    const int*   partner    = (const int*)  d_in[3];
    float*       out        = (float*)d_out;

    dim3 blk(256);
    dim3 grd(CCH / CPB, NB);
    fused_shuffle_kernel<<<grd, blk>>>(x, s_ca, rand_index, partner, out);
}

// round 4
// speedup vs baseline: 1.0769x; 1.0769x over previous
#include <cuda_runtime.h>
#include <cuda_bf16.h>
#include <stdint.h>

// Problem constants (fixed by the dataset):
//   x:          (80, 2048, 16, 16) f32
//   s_ca:       (80, 2048, 1, 1)   f32
//   rand_index: (80, 512)          int32
//   partner:    (80,)              int32
//   out:        (160, 2048, 16, 16) f32
#define NB    80
#define CCH   2048
#define NQ    64        // HW/4 float4 per channel
#define SSH   512
#define NBUCK 2048

// Descending stable rank of channel ch within row n (0..2047).
// rank < 512  <=>  in jax top_k, at list position k = rank.
__device__ int g_pos[NB * CCH];

// ---------------------------------------------------------------------------
// Kernel 1: per-row exact ranks via bucket counting sort.
// Scores ~ Uniform[0,1) => bucket = min(int(v*2048), 2047) is monotone with
// ~1 element per bucket. rank(ch) = #{buckets above} + within-bucket exact
// count using jax's stable tie-break (s_i > s_ch, or equal and i < ch).
// One block per row, 1024 threads, 2 elements/thread.
// ---------------------------------------------------------------------------
__global__ void __launch_bounds__(1024, 1)
rank_kernel(const float* __restrict__ s_ca)
{
    __shared__ float          ss[CCH];
    __shared__ int            hist[NBUCK];   // original bucket counts
    __shared__ int            off[NBUCK];    // # elements in strictly higher buckets
    __shared__ int            cnt[NBUCK];    // scatter cursors
    __shared__ unsigned short sidx[CCH];     // element ids grouped by bucket (desc)
    __shared__ int            wsum[32];

    const int n = blockIdx.x;
    const int t = threadIdx.x;
    const int lane = t & 31;
    const int w    = t >> 5;

    const float* row = s_ca + (size_t)n * CCH;

    // Phase 0: load + zero
#pragma unroll
    for (int i = t; i < CCH; i += 1024) ss[i] = row[i];
#pragma unroll
    for (int i = t; i < NBUCK; i += 1024) { hist[i] = 0; cnt[i] = 0; }
    __syncthreads();

    // Phase 1: histogram
#pragma unroll
    for (int i = t; i < CCH; i += 1024) {
        int b = (int)(ss[i] * (float)NBUCK);
        b = b > NBUCK - 1 ? NBUCK - 1 : b;
        atomicAdd(&hist[b], 1);
    }
    __syncthreads();

    // Phase 2: inclusive prefix over ascending buckets -> off[b] = N - incl[b]
    // Thread t owns bins 2t, 2t+1.
    int h0 = hist[2 * t], h1 = hist[2 * t + 1];
    int pair = h0 + h1;
    int incl = pair;
#pragma unroll
    for (int o = 1; o < 32; o <<= 1) {
        int v = __shfl_up_sync(0xFFFFFFFFu, incl, o);
        if (lane >= o) incl += v;
    }
    if (lane == 31) wsum[w] = incl;
    __syncthreads();
    if (w == 0) {
        int v = wsum[lane];
        int iv = v;
#pragma unroll
        for (int o = 1; o < 32; o <<= 1) {
            int u = __shfl_up_sync(0xFFFFFFFFu, iv, o);
            if (lane >= o) iv += u;
        }
        wsum[lane] = iv - v;   // exclusive warp offsets
    }
    __syncthreads();
    incl += wsum[w];
    off[2 * t]     = CCH - (incl - h1);
    off[2 * t + 1] = CCH - incl;
    __syncthreads();

    // Phase 3: scatter element ids grouped by bucket
#pragma unroll
    for (int i = t; i < CCH; i += 1024) {
        int b = (int)(ss[i] * (float)NBUCK);
        b = b > NBUCK - 1 ? NBUCK - 1 : b;
        int p = off[b] + atomicAdd(&cnt[b], 1);
        sidx[p] = (unsigned short)i;
    }
    __syncthreads();

    // Phase 4: exact rank per channel
#pragma unroll
    for (int ch = t; ch < CCH; ch += 1024) {
        float v = ss[ch];
        int b = (int)(v * (float)NBUCK);
        b = b > NBUCK - 1 ? NBUCK - 1 : b;
        int r = off[b];
        int e = off[b] + hist[b];
        for (int p = off[b]; p < e; ++p) {
            int i = sidx[p];
            float u = ss[i];
            r += (u > v) || (u == v && i < ch);
        }
        g_pos[n * CCH + ch] = r;
    }
}

// ---------------------------------------------------------------------------
// Kernel 2 (round-1 proven version): both output halves from one x read.
// ---------------------------------------------------------------------------
__global__ void __launch_bounds__(256)
shuffle_kernel(const float* __restrict__ x,
               const float* __restrict__ s_ca,
               const int*   __restrict__ rand_index,
               const int*   __restrict__ partner,
               float*       __restrict__ out)
{
    const int q   = threadIdx.x;                 // 0..63 (float4 within channel)
    const int ch  = blockIdx.x * 4 + threadIdx.y;
    const int n   = blockIdx.y;                  // source batch row 0..79

    const float4* x4 = (const float4*)x;
    float4*       o4 = (float4*)out;

    const size_t src_off = ((size_t)n * CCH + ch) * NQ + q;
    float4 xv = x4[src_off];
    float  s  = s_ca[n * CCH + ch];

    const int v = n >> 4;          // way
    const int b = n & 15;          // slot within way
    const size_t plain_off = (((size_t)(v * 32 + b))      * CCH + ch) * NQ + q;
    const size_t aug_off   = (((size_t)(v * 32 + 16 + b)) * CCH + ch) * NQ + q;

    float4 po;
    po.x = xv.x * s; po.y = xv.y * s; po.z = xv.z * s; po.w = xv.w * s;
    o4[plain_off] = po;

    float4 ao = po;
    const int k = g_pos[n * CCH + ch];     // uniform across the warp
    if (k < SSH) {
        int jrow = (n + 1 + partner[n]) % NB;
        int rc   = rand_index[n * SSH + k];
        float4 pv = x4[((size_t)jrow * CCH + rc) * NQ + q];
        ao.x = (0.7f * xv.x + 0.3f * pv.x) * s;
        ao.y = (0.7f * xv.y + 0.3f * pv.y) * s;
        ao.z = (0.7f * xv.z + 0.3f * pv.z) * s;
        ao.w = (0.7f * xv.w + 0.3f * pv.w) * s;
    }
    o4[aug_off] = ao;
}

extern "C" void kernel_launch(void* const* d_in, const int* in_sizes, int n_in,
                              void* d_out, int out_size)
{
    const float* x          = (const float*)d_in[0];
    const float* s_ca       = (const float*)d_in[1];
    const int*   rand_index = (const int*)  d_in[2];
    const int*   partner    = (const int*)  d_in[3];
    float*       out        = (float*)d_out;

    rank_kernel<<<NB, 1024>>>(s_ca);

    dim3 blk(64, 4);
    dim3 grd(CCH / 4, NB);
    shuffle_kernel<<<grd, blk>>>(x, s_ca, rand_index, partner, out);
}